// round 8
// baseline (speedup 1.0000x reference)
#include <cuda_runtime.h>
#include <cuda_bf16.h>
#include <float.h>

// Problem constants
#define BB   256      // batch
#define TOK  256      // tokens per image
#define NQ   (BB*TOK) // 65536 queries
#define V    1024     // codebook size
#define D    256      // code dim

// Device scratch (allocation-free rule: __device__ globals).
__device__ __align__(16) float g_A[V * V];   // A[r][v] = ||w_v||^2 - 2 w_r . w_v  (4 MB)
__device__ __align__(16) int   g_idx[NQ];    // argmin per query (original order)
__device__ __align__(16) int   g_i[NQ];      // decoded seq1 indices
__device__ __align__(16) int   g_j[NQ];      // decoded seq2 indices
__device__ __align__(16) int   g_cnt[V];     // bucket counts (by i)
__device__ __align__(16) int   g_off[V];     // exclusive bucket offsets
__device__ __align__(16) int   g_pos[V];     // scatter cursors
__device__ __align__(16) int   g_qn[NQ];     // query ids sorted by i
__device__ __align__(16) int   g_qj[NQ];     // j of sorted queries
__device__ int g_is64;                       // 1 if inputs are int64-layout

// ---------------------------------------------------------------------------
// k_detect: sniff index dtype (int64 <=> odd int32 words all zero & even < V
// over first 256 words). Also re-zeros sort counters (graph is replayed, so
// every launch must reset its own state).
// ---------------------------------------------------------------------------
__global__ void k_detect(const int* __restrict__ s1) {
    __shared__ int bad;
    if (threadIdx.x == 0) bad = 0;
    __syncthreads();
    int t = threadIdx.x;             // 0..255
    int w = s1[t];
    if (t & 1) { if (w != 0) atomicOr(&bad, 1); }
    else       { if ((unsigned)w >= V) atomicOr(&bad, 1); }
    for (int q = t; q < V; q += 256) { g_cnt[q] = 0; g_pos[q] = 0; }
    __syncthreads();
    if (t == 0) g_is64 = bad ? 0 : 1;
}

// ---------------------------------------------------------------------------
// k_convert: decode indices (both layouts), clamp, and histogram by i.
// ---------------------------------------------------------------------------
__global__ void k_convert(const int* __restrict__ s1, const int* __restrict__ s2) {
    int n = blockIdx.x * blockDim.x + threadIdx.x;   // covers NQ
    int sh = g_is64;
    int a = s1[n << sh];
    int b = s2[n << sh];
    a = min(max(a, 0), V - 1);
    b = min(max(b, 0), V - 1);
    g_i[n] = a;
    g_j[n] = b;
    atomicAdd(&g_cnt[a], 1);
}

// ---------------------------------------------------------------------------
// k_scan: single-CTA exclusive prefix sum over the 1024 bucket counts.
// ---------------------------------------------------------------------------
__global__ __launch_bounds__(1024) void k_scan() {
    __shared__ int s[V];
    int t = threadIdx.x;
    int v = g_cnt[t];
    s[t] = v;
    __syncthreads();
    #pragma unroll
    for (int off = 1; off < V; off <<= 1) {
        int x = (t >= off) ? s[t - off] : 0;
        __syncthreads();
        s[t] += x;
        __syncthreads();
    }
    g_off[t] = s[t] - v;   // exclusive
}

// ---------------------------------------------------------------------------
// k_scatter: counting-sort queries into i-buckets.
// ---------------------------------------------------------------------------
__global__ void k_scatter() {
    int n = blockIdx.x * blockDim.x + threadIdx.x;
    int i = g_i[n];
    int p = g_off[i] + atomicAdd(&g_pos[i], 1);
    g_qn[p] = n;
    g_qj[p] = g_j[n];
}

// ---------------------------------------------------------------------------
// k_gemmA: A[r][v] = ||w_v||^2 - 2 * dot(W[r], W[v]).
// 64x64 tile per CTA, 256 threads, 4x4 register tile, BK=16.
// Row norms fused: the B-tile loader accumulates sum(w^2) over the k it
// streams; 4 loader threads per row combine via smem in the epilogue.
// ---------------------------------------------------------------------------
__global__ __launch_bounds__(256) void k_gemmA(const float* __restrict__ W) {
    __shared__ __align__(16) float As[16][64];   // [k][r]
    __shared__ __align__(16) float Bs[16][64];   // [k][v]
    __shared__ float ns[64][4];                  // partial row norms (v tile)

    int tid = threadIdx.x;
    int tx = tid & 15;             // v direction
    int ty = tid >> 4;             // r direction
    int r0 = blockIdx.y * 64;
    int v0 = blockIdx.x * 64;

    float acc[4][4];
    #pragma unroll
    for (int i = 0; i < 4; i++)
        #pragma unroll
        for (int j = 0; j < 4; j++) acc[i][j] = 0.f;

    int lrow = tid >> 2;           // 0..63
    int lk4  = (tid & 3) * 4;      // 0,4,8,12
    float bn = 0.f;                // partial ||w_{v0+lrow}||^2 over loaded k

    for (int kt = 0; kt < D; kt += 16) {
        #pragma unroll
        for (int u = 0; u < 4; u++) {
            float av = W[(r0 + lrow) * D + kt + lk4 + u];
            float bv = W[(v0 + lrow) * D + kt + lk4 + u];
            As[lk4 + u][lrow] = av;
            Bs[lk4 + u][lrow] = bv;
            bn = fmaf(bv, bv, bn);
        }
        __syncthreads();
        #pragma unroll
        for (int kk = 0; kk < 16; kk++) {
            float ar[4], br[4];
            #pragma unroll
            for (int i = 0; i < 4; i++) ar[i] = As[kk][ty * 4 + i];
            #pragma unroll
            for (int j = 0; j < 4; j++) br[j] = Bs[kk][tx * 4 + j];
            #pragma unroll
            for (int i = 0; i < 4; i++)
                #pragma unroll
                for (int j = 0; j < 4; j++)
                    acc[i][j] = fmaf(ar[i], br[j], acc[i][j]);
        }
        __syncthreads();
    }

    ns[lrow][tid & 3] = bn;
    __syncthreads();

    #pragma unroll
    for (int j = 0; j < 4; j++) {
        int vv = tx * 4 + j;
        float dv = ns[vv][0] + ns[vv][1] + ns[vv][2] + ns[vv][3];
        int v = v0 + vv;
        #pragma unroll
        for (int i = 0; i < 4; i++) {
            int r = r0 + ty * 4 + i;
            g_A[r * V + v] = dv - 2.0f * acc[i][j];
        }
    }
}

// ---------------------------------------------------------------------------
// k_argmin2: one CTA per i-bucket. A[i] row cached in smem (4 KB); each warp
// handles one bucket query at a time, streaming only A[j] from L2.
// score(v) = c1*A[i][v] + c2*A[j][v]; strict < keeps the first minimum per
// lane, cross-lane tie-break takes the lower index => exact argmin semantics.
// ---------------------------------------------------------------------------
__global__ __launch_bounds__(256) void k_argmin2(const float* __restrict__ alpha) {
    __shared__ __align__(16) float ai[V];
    int b = blockIdx.x;
    int t = threadIdx.x;

    ((float4*)ai)[t] = ((const float4*)(g_A + b * V))[t];   // 256 x 16B = 4 KB
    __syncthreads();

    float a  = alpha[0];
    float c1 = 1.0f - a;
    float c2 = a;
    int off = g_off[b];
    int cnt = g_cnt[b];
    int warp = t >> 5, lane = t & 31;

    for (int q = warp; q < cnt; q += 8) {
        int n = g_qn[off + q];
        int j = g_qj[off + q];
        const float4* Aj = (const float4*)(g_A + j * V);
        const float4* Ai = (const float4*)ai;

        float best = FLT_MAX;
        int bidx = 0;
        #pragma unroll
        for (int k = 0; k < 8; k++) {
            int vb = k * 128 + lane * 4;
            float4 x = Ai[k * 32 + lane];
            float4 y = Aj[k * 32 + lane];
            float s;
            s = fmaf(c2, y.x, c1 * x.x); if (s < best) { best = s; bidx = vb;     }
            s = fmaf(c2, y.y, c1 * x.y); if (s < best) { best = s; bidx = vb + 1; }
            s = fmaf(c2, y.z, c1 * x.z); if (s < best) { best = s; bidx = vb + 2; }
            s = fmaf(c2, y.w, c1 * x.w); if (s < best) { best = s; bidx = vb + 3; }
        }
        #pragma unroll
        for (int o = 16; o > 0; o >>= 1) {
            float ob = __shfl_xor_sync(0xffffffffu, best, o);
            int   oi = __shfl_xor_sync(0xffffffffu, bidx, o);
            if (ob < best || (ob == best && oi < bidx)) { best = ob; bidx = oi; }
        }
        if (lane == 0) g_idx[n] = bidx;
    }
}

// ---------------------------------------------------------------------------
// k_gather: out[b][d][t] = W[idx[b][t]][d]. CTA = 8 b's x 8 d's.
// Reads W directly: 8 consecutive d's per code row = one 32B sector, so the
// smem stage needs no separate transpose kernel. +4 pad keeps the staging
// stores bank-conflict-free. Output writes are coalesced 1 KB runs.
// ---------------------------------------------------------------------------
__global__ __launch_bounds__(256) void k_gather(const float* __restrict__ W,
                                                float* __restrict__ out) {
    __shared__ float wt_s[8][V + 4];               // ~32 KB
    __shared__ __align__(16) int idx_s[8][TOK];    // 8 KB

    int t  = threadIdx.x;            // 0..255
    int b0 = blockIdx.x * 8;
    int d0 = blockIdx.y * 8;

    #pragma unroll
    for (int q = 0; q < 32; q++) {
        int lin = q * 256 + t;       // 0..8191
        int v  = lin >> 3;           // code row
        int dl = lin & 7;            // d offset
        wt_s[dl][v] = W[v * D + d0 + dl];
    }
    #pragma unroll
    for (int q = 0; q < 8; q++) {
        int lin = q * 256 + t;
        int bl = lin >> 8, tt = lin & 255;
        idx_s[bl][tt] = g_idx[(b0 + bl) * TOK + tt];
    }
    __syncthreads();

    #pragma unroll
    for (int bl = 0; bl < 8; bl++) {
        int myidx = idx_s[bl][t];
        #pragma unroll
        for (int dl = 0; dl < 8; dl++) {
            out[(((long)(b0 + bl) * D) + (d0 + dl)) * TOK + t] = wt_s[dl][myidx];
        }
    }
}

// ---------------------------------------------------------------------------
extern "C" void kernel_launch(void* const* d_in, const int* in_sizes, int n_in,
                              void* d_out, int out_size) {
    const int*   seq1  = (const int*)d_in[0];    // int32 words (int64 via g_is64)
    const int*   seq2  = (const int*)d_in[1];
    const float* alpha = (const float*)d_in[2];
    const float* W     = (const float*)d_in[3];
    float* out = (float*)d_out;

    k_detect<<<1, 256>>>(seq1);                   // dtype sniff + zero counters
    k_convert<<<NQ / 256, 256>>>(seq1, seq2);     // decode + clamp + histogram
    k_scan<<<1, 1024>>>();                        // bucket offsets
    k_scatter<<<NQ / 256, 256>>>();               // sort queries by i
    dim3 ggrid(V / 64, V / 64);
    k_gemmA<<<ggrid, 256>>>(W);                   // A table + fused row norms
    k_argmin2<<<V, 256>>>(alpha);                 // CTA per bucket, A[i] in smem
    dim3 grid(BB / 8, D / 8);
    k_gather<<<grid, 256>>>(W, out);              // gather + BCHW layout
}

// round 10
// speedup vs baseline: 1.0213x; 1.0213x over previous
#include <cuda_runtime.h>
#include <cuda_bf16.h>
#include <float.h>

// Problem constants
#define BB   256      // batch
#define TOK  256      // tokens per image
#define NQ   (BB*TOK) // 65536 queries
#define V    1024     // codebook size
#define D    256      // code dim

// Device scratch (allocation-free rule: __device__ globals).
__device__ __align__(16) float g_A[V * V];   // A[r][v] = ||w_v||^2 - 2 w_r . w_v  (4 MB)
__device__ __align__(16) int   g_idx[NQ];    // argmin per query (original order)
__device__ __align__(16) int   g_i[NQ];      // decoded seq1 indices
__device__ __align__(16) int   g_j[NQ];      // decoded seq2 indices
__device__ __align__(16) int   g_cnt[V];     // bucket counts (by i)
__device__ __align__(16) int   g_off[V];     // exclusive bucket offsets
__device__ __align__(16) int   g_pos[V];     // reservation cursors
__device__ __align__(16) int   g_qn[NQ];     // query ids grouped by i
__device__ __align__(16) int   g_qj[NQ];     // j of grouped queries
__device__ int g_is64;                       // 1 if inputs are int64-layout

// ---------------------------------------------------------------------------
// k_detect: sniff index dtype (int64 <=> odd int32 words all zero & even < V
// over first 256 words) and zero the sort counters (graph is replayed; every
// launch must reset its own state).
// ---------------------------------------------------------------------------
__global__ void k_detect(const int* __restrict__ s1) {
    __shared__ int bad;
    if (threadIdx.x == 0) bad = 0;
    __syncthreads();
    int t = threadIdx.x;             // 0..255
    int w = s1[t];
    if (t & 1) { if (w != 0) atomicOr(&bad, 1); }
    else       { if ((unsigned)w >= V) atomicOr(&bad, 1); }
    for (int q = t; q < V; q += 256) { g_cnt[q] = 0; g_pos[q] = 0; }
    __syncthreads();
    if (t == 0) g_is64 = bad ? 0 : 1;
}

// ---------------------------------------------------------------------------
// k_decode_hist: decode indices (both layouts), clamp, store g_i/g_j, and
// histogram by i using a PRIVATE smem histogram per CTA; one coalesced
// global atomicAdd per nonzero bin per CTA at the end.
// Grid: 32 CTAs x 256 threads x 8 items.
// ---------------------------------------------------------------------------
__global__ __launch_bounds__(256) void k_decode_hist(const int* __restrict__ s1,
                                                     const int* __restrict__ s2) {
    __shared__ int lh[V];
    int t = threadIdx.x;
    for (int v = t; v < V; v += 256) lh[v] = 0;
    __syncthreads();

    int sh = g_is64;
    int base = blockIdx.x * 2048;
    #pragma unroll
    for (int q = 0; q < 8; q++) {
        int n = base + q * 256 + t;
        int a = s1[n << sh];
        int b = s2[n << sh];
        a = min(max(a, 0), V - 1);
        b = min(max(b, 0), V - 1);
        g_i[n] = a;
        g_j[n] = b;
        atomicAdd(&lh[a], 1);          // ATOMS, spread addresses: cheap
    }
    __syncthreads();
    for (int v = t; v < V; v += 256) {
        int c = lh[v];
        if (c) atomicAdd(&g_cnt[v], c); // coalesced, no-return use => REDG-class
    }
}

// ---------------------------------------------------------------------------
// k_scan: single-CTA exclusive prefix sum over the 1024 bucket counts.
// ---------------------------------------------------------------------------
__global__ __launch_bounds__(1024) void k_scan() {
    __shared__ int s[V];
    int t = threadIdx.x;
    int v = g_cnt[t];
    s[t] = v;
    __syncthreads();
    #pragma unroll
    for (int off = 1; off < V; off <<= 1) {
        int x = (t >= off) ? s[t - off] : 0;
        __syncthreads();
        s[t] += x;
        __syncthreads();
    }
    g_off[t] = s[t] - v;   // exclusive
}

// ---------------------------------------------------------------------------
// k_scatter: counting-sort queries into i-buckets with smem privatization.
// Phase A: local rank per item via smem atomics.
// Phase B: one returning global atomicAdd per CTA-bucket reserves a range.
// Phase C: scatter items into the reserved ranges.
// Order within a bucket is irrelevant (g_idx is written keyed by original n).
// Grid: 16 CTAs x 256 threads x 16 items.
// ---------------------------------------------------------------------------
__global__ __launch_bounds__(256) void k_scatter() {
    __shared__ int lh[V];
    __shared__ int sbase[V];
    int t = threadIdx.x;
    for (int v = t; v < V; v += 256) lh[v] = 0;
    __syncthreads();

    int base = blockIdx.x * 4096;
    int iv[16], jv[16], lrank[16];
    #pragma unroll
    for (int q = 0; q < 16; q++) {
        int n = base + q * 256 + t;
        iv[q] = g_i[n];
        jv[q] = g_j[n];
        lrank[q] = atomicAdd(&lh[iv[q]], 1);
    }
    __syncthreads();
    for (int v = t; v < V; v += 256) {
        int c = lh[v];
        sbase[v] = c ? (g_off[v] + atomicAdd(&g_pos[v], c)) : 0;
    }
    __syncthreads();
    #pragma unroll
    for (int q = 0; q < 16; q++) {
        int n = base + q * 256 + t;
        int p = sbase[iv[q]] + lrank[q];
        g_qn[p] = n;
        g_qj[p] = jv[q];
    }
}

// ---------------------------------------------------------------------------
// k_gemmA: A[r][v] = ||w_v||^2 - 2 * dot(W[r], W[v]).
// 64x64 tile per CTA, 256 threads, 4x4 register tile, BK=16.
// Row norms fused into the B-tile loader.
// ---------------------------------------------------------------------------
__global__ __launch_bounds__(256) void k_gemmA(const float* __restrict__ W) {
    __shared__ __align__(16) float As[16][64];   // [k][r]
    __shared__ __align__(16) float Bs[16][64];   // [k][v]
    __shared__ float ns[64][4];                  // partial row norms (v tile)

    int tid = threadIdx.x;
    int tx = tid & 15;             // v direction
    int ty = tid >> 4;             // r direction
    int r0 = blockIdx.y * 64;
    int v0 = blockIdx.x * 64;

    float acc[4][4];
    #pragma unroll
    for (int i = 0; i < 4; i++)
        #pragma unroll
        for (int j = 0; j < 4; j++) acc[i][j] = 0.f;

    int lrow = tid >> 2;           // 0..63
    int lk4  = (tid & 3) * 4;      // 0,4,8,12
    float bn = 0.f;

    for (int kt = 0; kt < D; kt += 16) {
        #pragma unroll
        for (int u = 0; u < 4; u++) {
            float av = W[(r0 + lrow) * D + kt + lk4 + u];
            float bv = W[(v0 + lrow) * D + kt + lk4 + u];
            As[lk4 + u][lrow] = av;
            Bs[lk4 + u][lrow] = bv;
            bn = fmaf(bv, bv, bn);
        }
        __syncthreads();
        #pragma unroll
        for (int kk = 0; kk < 16; kk++) {
            float ar[4], br[4];
            #pragma unroll
            for (int i = 0; i < 4; i++) ar[i] = As[kk][ty * 4 + i];
            #pragma unroll
            for (int j = 0; j < 4; j++) br[j] = Bs[kk][tx * 4 + j];
            #pragma unroll
            for (int i = 0; i < 4; i++)
                #pragma unroll
                for (int j = 0; j < 4; j++)
                    acc[i][j] = fmaf(ar[i], br[j], acc[i][j]);
        }
        __syncthreads();
    }

    ns[lrow][tid & 3] = bn;
    __syncthreads();

    #pragma unroll
    for (int j = 0; j < 4; j++) {
        int vv = tx * 4 + j;
        float dv = ns[vv][0] + ns[vv][1] + ns[vv][2] + ns[vv][3];
        int v = v0 + vv;
        #pragma unroll
        for (int i = 0; i < 4; i++) {
            int r = r0 + ty * 4 + i;
            g_A[r * V + v] = dv - 2.0f * acc[i][j];
        }
    }
}

// ---------------------------------------------------------------------------
// k_argmin2: one CTA per i-bucket. A[i] cached in smem (4 KB); each warp
// handles one bucket query at a time, streaming only A[j] from L2.
// score(v) = c1*A[i][v] + c2*A[j][v]; strict < keeps the first minimum per
// lane, cross-lane tie-break takes the lower index => exact argmin semantics.
// ---------------------------------------------------------------------------
__global__ __launch_bounds__(256) void k_argmin2(const float* __restrict__ alpha) {
    __shared__ __align__(16) float ai[V];
    int b = blockIdx.x;
    int t = threadIdx.x;

    ((float4*)ai)[t] = ((const float4*)(g_A + b * V))[t];   // 256 x 16B = 4 KB
    __syncthreads();

    float a  = alpha[0];
    float c1 = 1.0f - a;
    float c2 = a;
    int off = g_off[b];
    int cnt = g_cnt[b];
    int warp = t >> 5, lane = t & 31;

    for (int q = warp; q < cnt; q += 8) {
        int n = g_qn[off + q];
        int j = g_qj[off + q];
        const float4* Aj = (const float4*)(g_A + j * V);
        const float4* Ai = (const float4*)ai;

        float best = FLT_MAX;
        int bidx = 0;
        #pragma unroll
        for (int k = 0; k < 8; k++) {
            int vb = k * 128 + lane * 4;
            float4 x = Ai[k * 32 + lane];
            float4 y = Aj[k * 32 + lane];
            float s;
            s = fmaf(c2, y.x, c1 * x.x); if (s < best) { best = s; bidx = vb;     }
            s = fmaf(c2, y.y, c1 * x.y); if (s < best) { best = s; bidx = vb + 1; }
            s = fmaf(c2, y.z, c1 * x.z); if (s < best) { best = s; bidx = vb + 2; }
            s = fmaf(c2, y.w, c1 * x.w); if (s < best) { best = s; bidx = vb + 3; }
        }
        #pragma unroll
        for (int o = 16; o > 0; o >>= 1) {
            float ob = __shfl_xor_sync(0xffffffffu, best, o);
            int   oi = __shfl_xor_sync(0xffffffffu, bidx, o);
            if (ob < best || (ob == best && oi < bidx)) { best = ob; bidx = oi; }
        }
        if (lane == 0) g_idx[n] = bidx;
    }
}

// ---------------------------------------------------------------------------
// k_gather: out[b][d][t] = W[idx[b][t]][d]. CTA = 8 b's x 8 d's.
// W read directly (8 consecutive d's per code row = one 32B sector; W is
// L2-resident). Output writes are coalesced 1 KB runs.
// ---------------------------------------------------------------------------
__global__ __launch_bounds__(256) void k_gather(const float* __restrict__ W,
                                                float* __restrict__ out) {
    __shared__ float wt_s[8][V + 4];               // ~32 KB
    __shared__ __align__(16) int idx_s[8][TOK];    // 8 KB

    int t  = threadIdx.x;            // 0..255
    int b0 = blockIdx.x * 8;
    int d0 = blockIdx.y * 8;

    #pragma unroll
    for (int q = 0; q < 32; q++) {
        int lin = q * 256 + t;       // 0..8191
        int v  = lin >> 3;           // code row
        int dl = lin & 7;            // d offset
        wt_s[dl][v] = W[v * D + d0 + dl];
    }
    #pragma unroll
    for (int q = 0; q < 8; q++) {
        int lin = q * 256 + t;
        int bl = lin >> 8, tt = lin & 255;
        idx_s[bl][tt] = g_idx[(b0 + bl) * TOK + tt];
    }
    __syncthreads();

    #pragma unroll
    for (int bl = 0; bl < 8; bl++) {
        int myidx = idx_s[bl][t];
        #pragma unroll
        for (int dl = 0; dl < 8; dl++) {
            out[(((long)(b0 + bl) * D) + (d0 + dl)) * TOK + t] = wt_s[dl][myidx];
        }
    }
}

// ---------------------------------------------------------------------------
extern "C" void kernel_launch(void* const* d_in, const int* in_sizes, int n_in,
                              void* d_out, int out_size) {
    const int*   seq1  = (const int*)d_in[0];    // int32 words (int64 via g_is64)
    const int*   seq2  = (const int*)d_in[1];
    const float* alpha = (const float*)d_in[2];
    const float* W     = (const float*)d_in[3];
    float* out = (float*)d_out;

    k_detect<<<1, 256>>>(seq1);                   // dtype sniff + zero counters
    k_decode_hist<<<32, 256>>>(seq1, seq2);       // decode + smem histogram
    k_scan<<<1, 1024>>>();                        // bucket offsets
    k_scatter<<<16, 256>>>();                     // privatized counting sort
    dim3 ggrid(V / 64, V / 64);
    k_gemmA<<<ggrid, 256>>>(W);                   // A table + fused row norms
    k_argmin2<<<V, 256>>>(alpha);                 // CTA per bucket, A[i] in smem
    dim3 grid(BB / 8, D / 8);
    k_gather<<<grid, 256>>>(W, out);              // gather + BCHW layout
}

// round 11
// speedup vs baseline: 1.1234x; 1.1000x over previous
#include <cuda_runtime.h>
#include <cuda_bf16.h>
#include <float.h>

// Problem constants
#define BB   256      // batch
#define TOK  256      // tokens per image
#define NQ   (BB*TOK) // 65536 queries
#define V    1024     // codebook size
#define D    256      // code dim

// Device scratch (allocation-free rule: __device__ globals).
__device__ __align__(16) float          g_A[V * V];    // fp32 A[r][v] = ||w_v||^2 - 2 w_r.w_v (4 MB)
__device__ __align__(16) __nv_bfloat16  g_A16[V * V];  // bf16 copy of A (2 MB)
__device__ __align__(16) int            g_idx[NQ];     // argmin per query
__device__ __align__(16) int            g_i[NQ];       // decoded seq1 indices
__device__ __align__(16) int            g_j[NQ];       // decoded seq2 indices
__device__ int g_is64;                                 // 1 if inputs are int64-layout

// ---------------------------------------------------------------------------
// k_detect: sniff index dtype (int64 <=> odd int32 words all zero & even < V
// over first 256 words). Misclassification prob for int32 data ~(1/1024)^128.
// ---------------------------------------------------------------------------
__global__ void k_detect(const int* __restrict__ s1) {
    __shared__ int bad;
    if (threadIdx.x == 0) bad = 0;
    __syncthreads();
    int t = threadIdx.x;             // 0..255
    int w = s1[t];
    if (t & 1) { if (w != 0) atomicOr(&bad, 1); }
    else       { if ((unsigned)w >= V) atomicOr(&bad, 1); }
    __syncthreads();
    if (t == 0) g_is64 = bad ? 0 : 1;
}

// ---------------------------------------------------------------------------
// k_decode: decode indices (both layouts), clamp to [0, V-1].
// ---------------------------------------------------------------------------
__global__ void k_decode(const int* __restrict__ s1, const int* __restrict__ s2) {
    int n = blockIdx.x * blockDim.x + threadIdx.x;   // covers NQ
    int sh = g_is64;
    int a = s1[n << sh];
    int b = s2[n << sh];
    g_i[n] = min(max(a, 0), V - 1);
    g_j[n] = min(max(b, 0), V - 1);
}

// ---------------------------------------------------------------------------
// k_gemmA: A[r][v] = ||w_v||^2 - 2 * dot(W[r], W[v]); writes fp32 + bf16.
// 64x64 tile per CTA, 256 threads, 4x4 register tile, BK=16.
// Row norms fused into the B-tile loader.
// ---------------------------------------------------------------------------
__global__ __launch_bounds__(256) void k_gemmA(const float* __restrict__ W) {
    __shared__ __align__(16) float As[16][64];   // [k][r]
    __shared__ __align__(16) float Bs[16][64];   // [k][v]
    __shared__ float ns[64][4];                  // partial row norms (v tile)

    int tid = threadIdx.x;
    int tx = tid & 15;             // v direction
    int ty = tid >> 4;             // r direction
    int r0 = blockIdx.y * 64;
    int v0 = blockIdx.x * 64;

    float acc[4][4];
    #pragma unroll
    for (int i = 0; i < 4; i++)
        #pragma unroll
        for (int j = 0; j < 4; j++) acc[i][j] = 0.f;

    int lrow = tid >> 2;           // 0..63
    int lk4  = (tid & 3) * 4;      // 0,4,8,12
    float bn = 0.f;

    for (int kt = 0; kt < D; kt += 16) {
        #pragma unroll
        for (int u = 0; u < 4; u++) {
            float av = W[(r0 + lrow) * D + kt + lk4 + u];
            float bv = W[(v0 + lrow) * D + kt + lk4 + u];
            As[lk4 + u][lrow] = av;
            Bs[lk4 + u][lrow] = bv;
            bn = fmaf(bv, bv, bn);
        }
        __syncthreads();
        #pragma unroll
        for (int kk = 0; kk < 16; kk++) {
            float ar[4], br[4];
            #pragma unroll
            for (int i = 0; i < 4; i++) ar[i] = As[kk][ty * 4 + i];
            #pragma unroll
            for (int j = 0; j < 4; j++) br[j] = Bs[kk][tx * 4 + j];
            #pragma unroll
            for (int i = 0; i < 4; i++)
                #pragma unroll
                for (int j = 0; j < 4; j++)
                    acc[i][j] = fmaf(ar[i], br[j], acc[i][j]);
        }
        __syncthreads();
    }

    ns[lrow][tid & 3] = bn;
    __syncthreads();

    float dv[4];
    #pragma unroll
    for (int j = 0; j < 4; j++) {
        int vv = tx * 4 + j;
        dv[j] = ns[vv][0] + ns[vv][1] + ns[vv][2] + ns[vv][3];
    }

    #pragma unroll
    for (int i = 0; i < 4; i++) {
        int r = r0 + ty * 4 + i;
        float vals[4];
        #pragma unroll
        for (int j = 0; j < 4; j++) {
            vals[j] = dv[j] - 2.0f * acc[i][j];
            g_A[r * V + v0 + tx * 4 + j] = vals[j];
        }
        __nv_bfloat162* b2 = (__nv_bfloat162*)(g_A16 + (size_t)r * V + v0 + tx * 4);
        b2[0] = __floats2bfloat162_rn(vals[0], vals[1]);
        b2[1] = __floats2bfloat162_rn(vals[2], vals[3]);
    }
}

// ---------------------------------------------------------------------------
// k_argmin_bf16: warp per query.
// Phase 1: packed bf16 scan of c1*A16[i] + c2*A16[j] -> warp min VALUE m16
//          (no index tracking; 2 instr per bf16x2 pair).
// Phase 2: rescan register-held packed scores; any element <= m16 + 16 gets
//          an EXACT fp32 evaluation from g_A. |s16 - s| <= ~5 (|A| < 512 so
//          bf16 rounding <= 1/elem, two bf16 arith rounds <= 2, coeff <= 1),
//          so every possible true winner is inside the window. Exact
//          candidates reduced with strict-< + lowest-index => argmin
//          first-occurrence semantics.
// ---------------------------------------------------------------------------
__global__ __launch_bounds__(256) void k_argmin_bf16(const float* __restrict__ alpha) {
    int warp = threadIdx.x >> 5;
    int lane = threadIdx.x & 31;
    int n = blockIdx.x * 8 + warp;

    float a  = alpha[0];
    float c1 = 1.0f - a;
    float c2 = a;
    __nv_bfloat162 c1v = __float2bfloat162_rn(c1);
    __nv_bfloat162 c2v = __float2bfloat162_rn(c2);
    int i = g_i[n];
    int j = g_j[n];

    const uint4* Ai = (const uint4*)(g_A16 + (size_t)i * V);   // 128 uint4 per row
    const uint4* Aj = (const uint4*)(g_A16 + (size_t)j * V);

    __nv_bfloat162 s2[16];
    __nv_bfloat162 m2 = __float2bfloat162_rn(1e30f);

    #pragma unroll
    for (int k = 0; k < 4; k++) {
        uint4 xq = Ai[k * 32 + lane];
        uint4 yq = Aj[k * 32 + lane];
        unsigned xw[4] = {xq.x, xq.y, xq.z, xq.w};
        unsigned yw[4] = {yq.x, yq.y, yq.z, yq.w};
        #pragma unroll
        for (int w = 0; w < 4; w++) {
            __nv_bfloat162 x2 = *reinterpret_cast<__nv_bfloat162*>(&xw[w]);
            __nv_bfloat162 y2 = *reinterpret_cast<__nv_bfloat162*>(&yw[w]);
            __nv_bfloat162 s = __hfma2(c2v, y2, __hmul2(c1v, x2));
            s2[k * 4 + w] = s;
            m2 = __hmin2(m2, s);
        }
    }

    float m = fminf(__low2float(m2), __high2float(m2));
    #pragma unroll
    for (int o = 16; o > 0; o >>= 1)
        m = fminf(m, __shfl_xor_sync(0xffffffffu, m, o));
    float thr = m + 16.0f;

    const float* Afi = g_A + (size_t)i * V;
    const float* Afj = g_A + (size_t)j * V;
    float bestv = FLT_MAX;
    int   bidx  = 0x7fffffff;

    #pragma unroll
    for (int p = 0; p < 16; p++) {
        int k = p >> 2, w = p & 3;
        int v0 = ((k * 32 + lane) * 4 + w) * 2;   // element index of low half
        float lo = __low2float(s2[p]);
        float hi = __high2float(s2[p]);
        if (lo <= thr) {
            float e = fmaf(c2, Afj[v0], c1 * Afi[v0]);
            if (e < bestv || (e == bestv && v0 < bidx)) { bestv = e; bidx = v0; }
        }
        if (hi <= thr) {
            float e = fmaf(c2, Afj[v0 + 1], c1 * Afi[v0 + 1]);
            if (e < bestv || (e == bestv && v0 + 1 < bidx)) { bestv = e; bidx = v0 + 1; }
        }
    }

    #pragma unroll
    for (int o = 16; o > 0; o >>= 1) {
        float ov = __shfl_xor_sync(0xffffffffu, bestv, o);
        int   oi = __shfl_xor_sync(0xffffffffu, bidx, o);
        if (ov < bestv || (ov == bestv && oi < bidx)) { bestv = ov; bidx = oi; }
    }
    if (lane == 0) g_idx[n] = bidx;
}

// ---------------------------------------------------------------------------
// k_gather: out[b][d][t] = W[idx[b][t]][d]. CTA = 8 b's x 8 d's.
// W read directly (8 consecutive d's per code row = one 32B sector; W is
// L2-resident). Output writes are coalesced 1 KB runs.
// ---------------------------------------------------------------------------
__global__ __launch_bounds__(256) void k_gather(const float* __restrict__ W,
                                                float* __restrict__ out) {
    __shared__ float wt_s[8][V + 4];               // ~32 KB
    __shared__ __align__(16) int idx_s[8][TOK];    // 8 KB

    int t  = threadIdx.x;            // 0..255
    int b0 = blockIdx.x * 8;
    int d0 = blockIdx.y * 8;

    #pragma unroll
    for (int q = 0; q < 32; q++) {
        int lin = q * 256 + t;       // 0..8191
        int v  = lin >> 3;           // code row
        int dl = lin & 7;            // d offset
        wt_s[dl][v] = W[v * D + d0 + dl];
    }
    #pragma unroll
    for (int q = 0; q < 8; q++) {
        int lin = q * 256 + t;
        int bl = lin >> 8, tt = lin & 255;
        idx_s[bl][tt] = g_idx[(b0 + bl) * TOK + tt];
    }
    __syncthreads();

    #pragma unroll
    for (int bl = 0; bl < 8; bl++) {
        int myidx = idx_s[bl][t];
        #pragma unroll
        for (int dl = 0; dl < 8; dl++) {
            out[(((long)(b0 + bl) * D) + (d0 + dl)) * TOK + t] = wt_s[dl][myidx];
        }
    }
}

// ---------------------------------------------------------------------------
extern "C" void kernel_launch(void* const* d_in, const int* in_sizes, int n_in,
                              void* d_out, int out_size) {
    const int*   seq1  = (const int*)d_in[0];    // int32 words (int64 via g_is64)
    const int*   seq2  = (const int*)d_in[1];
    const float* alpha = (const float*)d_in[2];
    const float* W     = (const float*)d_in[3];
    float* out = (float*)d_out;

    k_detect<<<1, 256>>>(seq1);                   // 1: dtype sniff
    k_decode<<<NQ / 256, 256>>>(seq1, seq2);      // 2: decode + clamp
    dim3 ggrid(V / 64, V / 64);
    k_gemmA<<<ggrid, 256>>>(W);                   // 3: A table (fp32 + bf16)
    k_argmin_bf16<<<NQ / 8, 256>>>(alpha);        // 4: bf16 scan + exact refine
    dim3 grid(BB / 8, D / 8);
    k_gather<<<grid, 256>>>(W, out);              // 5: gather + BCHW layout
}

// round 15
// speedup vs baseline: 1.3477x; 1.1997x over previous
#include <cuda_runtime.h>
#include <cuda_bf16.h>
#include <float.h>

// Problem constants
#define BB   256      // batch
#define TOK  256      // tokens per image
#define NQ   (BB*TOK) // 65536 queries
#define V    1024     // codebook size
#define D    256      // code dim
#define NBLK 32       // 32 blocks of 32 codes per A row

// Device scratch (allocation-free rule: __device__ globals).
__device__ __align__(16) float g_A[V * V];        // A[r][v] = ||w_v||^2 - 2 w_r.w_v (4 MB)
__device__ __align__(16) float g_bmin[V * NBLK];  // per-row per-block exact fp32 min (128 KB)
__device__ __align__(16) int   g_idx[NQ];         // argmin per query
__device__ __align__(16) int   g_i[NQ];           // decoded seq1 indices
__device__ __align__(16) int   g_j[NQ];           // decoded seq2 indices
__device__ int g_is64;                            // 1 if inputs are int64-layout

// ---------------------------------------------------------------------------
// k_detect: sniff index dtype (int64 <=> odd int32 words all zero & even < V
// over first 256 words). Misclassification prob for int32 data ~(1/1024)^128.
// ---------------------------------------------------------------------------
__global__ void k_detect(const int* __restrict__ s1) {
    __shared__ int bad;
    if (threadIdx.x == 0) bad = 0;
    __syncthreads();
    int t = threadIdx.x;             // 0..255
    int w = s1[t];
    if (t & 1) { if (w != 0) atomicOr(&bad, 1); }
    else       { if ((unsigned)w >= V) atomicOr(&bad, 1); }
    __syncthreads();
    if (t == 0) g_is64 = bad ? 0 : 1;
}

// ---------------------------------------------------------------------------
// k_decode: decode indices (both layouts), clamp to [0, V-1].
// ---------------------------------------------------------------------------
__global__ void k_decode(const int* __restrict__ s1, const int* __restrict__ s2) {
    int n = blockIdx.x * blockDim.x + threadIdx.x;   // covers NQ
    int sh = g_is64;
    int a = s1[n << sh];
    int b = s2[n << sh];
    g_i[n] = min(max(a, 0), V - 1);
    g_j[n] = min(max(b, 0), V - 1);
}

// ---------------------------------------------------------------------------
// k_gemmA: A[r][v] = ||w_v||^2 - 2 * dot(W[r], W[v]).
// 64x64 tile per CTA, 256 threads, 4x4 register tile, BK=16.
// Row norms fused into the B-tile loader.
// ---------------------------------------------------------------------------
__global__ __launch_bounds__(256) void k_gemmA(const float* __restrict__ W) {
    __shared__ __align__(16) float As[16][64];   // [k][r]
    __shared__ __align__(16) float Bs[16][64];   // [k][v]
    __shared__ float ns[64][4];                  // partial row norms (v tile)

    int tid = threadIdx.x;
    int tx = tid & 15;             // v direction
    int ty = tid >> 4;             // r direction
    int r0 = blockIdx.y * 64;
    int v0 = blockIdx.x * 64;

    float acc[4][4];
    #pragma unroll
    for (int i = 0; i < 4; i++)
        #pragma unroll
        for (int j = 0; j < 4; j++) acc[i][j] = 0.f;

    int lrow = tid >> 2;           // 0..63
    int lk4  = (tid & 3) * 4;      // 0,4,8,12
    float bn = 0.f;

    for (int kt = 0; kt < D; kt += 16) {
        #pragma unroll
        for (int u = 0; u < 4; u++) {
            float av = W[(r0 + lrow) * D + kt + lk4 + u];
            float bv = W[(v0 + lrow) * D + kt + lk4 + u];
            As[lk4 + u][lrow] = av;
            Bs[lk4 + u][lrow] = bv;
            bn = fmaf(bv, bv, bn);
        }
        __syncthreads();
        #pragma unroll
        for (int kk = 0; kk < 16; kk++) {
            float ar[4], br[4];
            #pragma unroll
            for (int i = 0; i < 4; i++) ar[i] = As[kk][ty * 4 + i];
            #pragma unroll
            for (int j = 0; j < 4; j++) br[j] = Bs[kk][tx * 4 + j];
            #pragma unroll
            for (int i = 0; i < 4; i++)
                #pragma unroll
                for (int j = 0; j < 4; j++)
                    acc[i][j] = fmaf(ar[i], br[j], acc[i][j]);
        }
        __syncthreads();
    }

    ns[lrow][tid & 3] = bn;
    __syncthreads();

    #pragma unroll
    for (int j = 0; j < 4; j++) {
        int vv = tx * 4 + j;
        float dv = ns[vv][0] + ns[vv][1] + ns[vv][2] + ns[vv][3];
        int v = v0 + vv;
        #pragma unroll
        for (int i = 0; i < 4; i++) {
            int r = r0 + ty * 4 + i;
            g_A[r * V + v] = dv - 2.0f * acc[i][j];
        }
    }
}

// ---------------------------------------------------------------------------
// k_blkmin: g_bmin[r][b] = exact fp32 min over A[r][b*32 .. b*32+31].
// One warp per (r, b); lane reads one element (coalesced 128B), warp-min.
// V*NBLK = 32768 (r,b) pairs, 8 warps per CTA => 4096 CTAs.
// ---------------------------------------------------------------------------
__global__ __launch_bounds__(256) void k_blkmin() {
    int gid  = blockIdx.x * 8 + (threadIdx.x >> 5);  // (r,b) pair id
    int lane = threadIdx.x & 31;
    int r = gid >> 5;
    int b = gid & 31;
    float v = g_A[r * V + b * 32 + lane];
    #pragma unroll
    for (int o = 16; o > 0; o >>= 1)
        v = fminf(v, __shfl_xor_sync(0xffffffffu, v, o));
    if (lane == 0) g_bmin[gid] = v;
}

// ---------------------------------------------------------------------------
// k_argmin_bb: branch-and-bound argmin, one warp per query.
//   score(v)  = c1*A[i][v] + c2*A[j][v]   (exact fp32 via fmaf)
//   m_hat     = min(score(i), score(j))   -> upper bound on the global min
//   bound_b   = c1*bmin_i[b] + c2*bmin_j[b] <= min score in block b
// Scan only blocks with bound_b <= m_hat + 0.05 (margin covers the <=3e-4
// fp32 rounding in computing bound_b; all real score comparisons are exact).
// The block holding the true argmin always passes (bound <= min <= m_hat),
// and tied-min blocks pass too, so strict-< + lowest-index reduction over
// scanned blocks reproduces argmin's first-occurrence semantics exactly.
// ---------------------------------------------------------------------------
__global__ __launch_bounds__(256) void k_argmin_bb(const float* __restrict__ alpha) {
    int warp = threadIdx.x >> 5;
    int lane = threadIdx.x & 31;
    int n = blockIdx.x * 8 + warp;

    float a  = alpha[0];
    float c1 = 1.0f - a;
    float c2 = a;
    int i = g_i[n];
    int j = g_j[n];

    const float* Afi = g_A + (size_t)i * V;
    const float* Afj = g_A + (size_t)j * V;

    // upper bound from the two natural candidates (exact fp32)
    float sc = FLT_MAX;
    if (lane < 2) {
        int v = (lane == 0) ? i : j;
        sc = fmaf(c2, Afj[v], c1 * Afi[v]);
    }
    #pragma unroll
    for (int o = 16; o > 0; o >>= 1)
        sc = fminf(sc, __shfl_xor_sync(0xffffffffu, sc, o));
    float thr = sc + 0.05f;

    // per-block lower bounds (lane b handles block b)
    float bmi = g_bmin[i * NBLK + lane];
    float bmj = g_bmin[j * NBLK + lane];
    float bound = fmaf(c2, bmj, c1 * bmi);
    unsigned mask = __ballot_sync(0xffffffffu, bound <= thr);

    float bestv = FLT_MAX;
    int   bidx  = 0x7fffffff;

    while (mask) {
        int b = __ffs(mask) - 1;
        mask &= mask - 1;
        int v = b * 32 + lane;
        float e = fmaf(c2, Afj[v], c1 * Afi[v]);
        // ascending b + strict < keeps the earliest index per lane
        if (e < bestv) { bestv = e; bidx = v; }
    }

    #pragma unroll
    for (int o = 16; o > 0; o >>= 1) {
        float ov = __shfl_xor_sync(0xffffffffu, bestv, o);
        int   oi = __shfl_xor_sync(0xffffffffu, bidx, o);
        if (ov < bestv || (ov == bestv && oi < bidx)) { bestv = ov; bidx = oi; }
    }
    if (lane == 0) {
        // Defensive: mathematically unreachable (winner's block always passes);
        // keeps a hypothetical logic bug finite/measurable instead of OOB->NaN.
        if (bidx == 0x7fffffff) bidx = min(i, j);
        g_idx[n] = bidx;
    }
}

// ---------------------------------------------------------------------------
// k_gather: out[b][d][t] = W[idx[b][t]][d]. CTA = 8 b's x 8 d's.
// W read directly (8 consecutive d's per code row = one 32B sector; W is
// L2-resident). Output writes are coalesced 1 KB runs.
// ---------------------------------------------------------------------------
__global__ __launch_bounds__(256) void k_gather(const float* __restrict__ W,
                                                float* __restrict__ out) {
    __shared__ float wt_s[8][V + 4];               // ~32 KB
    __shared__ __align__(16) int idx_s[8][TOK];    // 8 KB

    int t  = threadIdx.x;            // 0..255
    int b0 = blockIdx.x * 8;
    int d0 = blockIdx.y * 8;

    #pragma unroll
    for (int q = 0; q < 32; q++) {
        int lin = q * 256 + t;       // 0..8191
        int v  = lin >> 3;           // code row
        int dl = lin & 7;            // d offset
        wt_s[dl][v] = W[v * D + d0 + dl];
    }
    #pragma unroll
    for (int q = 0; q < 8; q++) {
        int lin = q * 256 + t;
        int bl = lin >> 8, tt = lin & 255;
        idx_s[bl][tt] = g_idx[(b0 + bl) * TOK + tt];
    }
    __syncthreads();

    #pragma unroll
    for (int bl = 0; bl < 8; bl++) {
        int myidx = min(max(idx_s[bl][t], 0), V - 1);   // defensive clamp
        #pragma unroll
        for (int dl = 0; dl < 8; dl++) {
            out[(((long)(b0 + bl) * D) + (d0 + dl)) * TOK + t] = wt_s[dl][myidx];
        }
    }
}

// ---------------------------------------------------------------------------
extern "C" void kernel_launch(void* const* d_in, const int* in_sizes, int n_in,
                              void* d_out, int out_size) {
    const int*   seq1  = (const int*)d_in[0];    // int32 words (int64 via g_is64)
    const int*   seq2  = (const int*)d_in[1];
    const float* alpha = (const float*)d_in[2];
    const float* W     = (const float*)d_in[3];
    float* out = (float*)d_out;

    k_detect<<<1, 256>>>(seq1);                   // 1: dtype sniff
    k_decode<<<NQ / 256, 256>>>(seq1, seq2);      // 2: decode + clamp
    dim3 ggrid(V / 64, V / 64);
    k_gemmA<<<ggrid, 256>>>(W);                   // 3: A table + fused norms
    k_blkmin<<<(V * NBLK) / 8, 256>>>();          // 4: per-block minima (4096 CTAs)
    k_argmin_bb<<<NQ / 8, 256>>>(alpha);          // 5: branch-and-bound argmin
    dim3 grid(BB / 8, D / 8);
    k_gather<<<grid, 256>>>(W, out);              // 6: gather + BCHW layout
}

// round 16
// speedup vs baseline: 1.5558x; 1.1544x over previous
#include <cuda_runtime.h>
#include <cuda_bf16.h>
#include <float.h>

// Problem constants
#define BB   256      // batch
#define TOK  256      // tokens per image
#define NQ   (BB*TOK) // 65536 queries
#define V    1024     // codebook size
#define D    256      // code dim
#define NBLK 32       // 32 blocks of 32 codes per A row
#define NTIL 16       // 1024/64 tiles per dimension
#define NTRI 136      // NTIL*(NTIL+1)/2 upper-triangle tiles

// Device scratch (allocation-free rule: __device__ globals).
__device__ __align__(16) float g_A[V * V];        // A[r][v] = ||w_v||^2 - 2 w_r.w_v (4 MB)
__device__ __align__(16) float g_bmin[V * NBLK];  // per-row per-block exact fp32 min (128 KB)
__device__ __align__(16) int   g_idx[NQ];         // argmin per query
__device__ __align__(16) int   g_i[NQ];           // decoded seq1 indices
__device__ __align__(16) int   g_j[NQ];           // decoded seq2 indices

// ---------------------------------------------------------------------------
// k_decode: detect index dtype per-CTA (redundant, branch-free result) and
// decode + clamp. int64 layout <=> odd int32 words all zero AND even words
// < V over the first 256 words (misclassify prob ~(1/1024)^128 for int32).
// First-256-word reads are L2 hits for all but the first CTA.
// ---------------------------------------------------------------------------
__global__ __launch_bounds__(256) void k_decode(const int* __restrict__ s1,
                                                const int* __restrict__ s2) {
    __shared__ int bad;
    int t = threadIdx.x;             // 0..255
    if (t == 0) bad = 0;
    __syncthreads();
    int w = s1[t];
    if (t & 1) { if (w != 0) atomicOr(&bad, 1); }
    else       { if ((unsigned)w >= V) atomicOr(&bad, 1); }
    __syncthreads();
    int sh = bad ? 0 : 1;            // 0: int32 layout, 1: int64 (low word)

    int n = blockIdx.x * 256 + t;    // covers NQ
    int a = s1[n << sh];
    int b = s2[n << sh];
    g_i[n] = min(max(a, 0), V - 1);
    g_j[n] = min(max(b, 0), V - 1);
}

// ---------------------------------------------------------------------------
// k_gemmA_tri: symmetric-aware A build. dot(W[r],W[v]) is symmetric, so only
// the upper-triangle 64x64 tiles (bi <= bj) are computed; each CTA writes
//   direct:  A[r][v] = d_v - 2*dot   (r in bi-tile, v in bj-tile)
//   mirror:  A[v][r] = d_r - 2*dot
// Diagonal tiles double-write identical values (harmless). Row norms for both
// tile sides are computed by the loaders. 256 threads, 4x4 register tile,
// BK=16. All fp32 exact => downstream argmin semantics unchanged.
// ---------------------------------------------------------------------------
__global__ __launch_bounds__(256) void k_gemmA_tri(const float* __restrict__ W) {
    __shared__ __align__(16) float As[16][64];   // [k][r]
    __shared__ __align__(16) float Bs[16][64];   // [k][v]
    __shared__ float nsa[64][4];                 // partial norms, r side
    __shared__ float nsb[64][4];                 // partial norms, v side

    // triangle decode: blockIdx.x -> (bi, bj), bi <= bj
    int L = blockIdx.x;
    int bi = 0;
    while (L >= NTIL - bi) { L -= NTIL - bi; bi++; }
    int bj = bi + L;
    int r0 = bi * 64;
    int v0 = bj * 64;

    int tid = threadIdx.x;
    int tx = tid & 15;             // v direction
    int ty = tid >> 4;             // r direction

    float acc[4][4];
    #pragma unroll
    for (int i = 0; i < 4; i++)
        #pragma unroll
        for (int j = 0; j < 4; j++) acc[i][j] = 0.f;

    int lrow = tid >> 2;           // 0..63
    int lk4  = (tid & 3) * 4;      // 0,4,8,12
    float an = 0.f, bn = 0.f;

    for (int kt = 0; kt < D; kt += 16) {
        #pragma unroll
        for (int u = 0; u < 4; u++) {
            float av = W[(r0 + lrow) * D + kt + lk4 + u];
            float bv = W[(v0 + lrow) * D + kt + lk4 + u];
            As[lk4 + u][lrow] = av;
            Bs[lk4 + u][lrow] = bv;
            an = fmaf(av, av, an);
            bn = fmaf(bv, bv, bn);
        }
        __syncthreads();
        #pragma unroll
        for (int kk = 0; kk < 16; kk++) {
            float ar[4], br[4];
            #pragma unroll
            for (int i = 0; i < 4; i++) ar[i] = As[kk][ty * 4 + i];
            #pragma unroll
            for (int j = 0; j < 4; j++) br[j] = Bs[kk][tx * 4 + j];
            #pragma unroll
            for (int i = 0; i < 4; i++)
                #pragma unroll
                for (int j = 0; j < 4; j++)
                    acc[i][j] = fmaf(ar[i], br[j], acc[i][j]);
        }
        __syncthreads();
    }

    nsa[lrow][tid & 3] = an;
    nsb[lrow][tid & 3] = bn;
    __syncthreads();

    float dv[4], dr[4];
    #pragma unroll
    for (int u = 0; u < 4; u++) {
        int vv = tx * 4 + u;
        int rr = ty * 4 + u;
        dv[u] = nsb[vv][0] + nsb[vv][1] + nsb[vv][2] + nsb[vv][3];
        dr[u] = nsa[rr][0] + nsa[rr][1] + nsa[rr][2] + nsa[rr][3];
    }

    // direct: A[r][v0+tx*4 .. +3], one float4 per i
    #pragma unroll
    for (int i = 0; i < 4; i++) {
        int r = r0 + ty * 4 + i;
        float4 o;
        o.x = dv[0] - 2.0f * acc[i][0];
        o.y = dv[1] - 2.0f * acc[i][1];
        o.z = dv[2] - 2.0f * acc[i][2];
        o.w = dv[3] - 2.0f * acc[i][3];
        *(float4*)(g_A + (size_t)r * V + v0 + tx * 4) = o;
    }
    // mirror: A[v][r0+ty*4 .. +3], one float4 per j
    #pragma unroll
    for (int j = 0; j < 4; j++) {
        int v = v0 + tx * 4 + j;
        float4 o;
        o.x = dr[0] - 2.0f * acc[0][j];
        o.y = dr[1] - 2.0f * acc[1][j];
        o.z = dr[2] - 2.0f * acc[2][j];
        o.w = dr[3] - 2.0f * acc[3][j];
        *(float4*)(g_A + (size_t)v * V + r0 + ty * 4) = o;
    }
}

// ---------------------------------------------------------------------------
// k_blkmin: g_bmin[r][b] = exact fp32 min over A[r][b*32 .. b*32+31].
// One warp per ROW: 8 float4 loads per lane, local min-of-4, then 3
// independent shuffle stages over each 8-lane group (one 32-v block per
// group per chunk). 1024 warps total, ~100 instr/warp.
// ---------------------------------------------------------------------------
__global__ __launch_bounds__(256) void k_blkmin() {
    int r    = blockIdx.x * 8 + (threadIdx.x >> 5);  // row id, 0..1023
    int lane = threadIdx.x & 31;
    const float4* row = (const float4*)(g_A + (size_t)r * V);

    #pragma unroll
    for (int k = 0; k < 8; k++) {
        float4 x = row[k * 32 + lane];               // v = k*128 + lane*4 ..+3
        float m = fminf(fminf(x.x, x.y), fminf(x.z, x.w));
        // reduce within 8-lane groups (one 32-element block each)
        m = fminf(m, __shfl_xor_sync(0xffffffffu, m, 1));
        m = fminf(m, __shfl_xor_sync(0xffffffffu, m, 2));
        m = fminf(m, __shfl_xor_sync(0xffffffffu, m, 4));
        if ((lane & 7) == 0)
            g_bmin[r * NBLK + k * 4 + (lane >> 3)] = m;
    }
}

// ---------------------------------------------------------------------------
// k_argmin_bb: branch-and-bound argmin, one warp per query.
//   score(v)  = c1*A[i][v] + c2*A[j][v]   (exact fp32 via fmaf)
//   m_hat     = min(score(i), score(j))   -> upper bound on the global min
//   bound_b   = c1*bmin_i[b] + c2*bmin_j[b] <= min score in block b
// Scan only blocks with bound_b <= m_hat + 0.05 (margin covers the <=3e-4
// fp32 rounding in computing bound_b; all real score comparisons are exact).
// The block holding the true argmin always passes (bound <= min <= m_hat),
// and tied-min blocks pass too, so strict-< + lowest-index reduction over
// scanned blocks reproduces argmin's first-occurrence semantics exactly.
// ---------------------------------------------------------------------------
__global__ __launch_bounds__(256) void k_argmin_bb(const float* __restrict__ alpha) {
    int warp = threadIdx.x >> 5;
    int lane = threadIdx.x & 31;
    int n = blockIdx.x * 8 + warp;

    float a  = alpha[0];
    float c1 = 1.0f - a;
    float c2 = a;
    int i = g_i[n];
    int j = g_j[n];

    const float* Afi = g_A + (size_t)i * V;
    const float* Afj = g_A + (size_t)j * V;

    // upper bound from the two natural candidates (exact fp32)
    float sc = FLT_MAX;
    if (lane < 2) {
        int v = (lane == 0) ? i : j;
        sc = fmaf(c2, Afj[v], c1 * Afi[v]);
    }
    #pragma unroll
    for (int o = 16; o > 0; o >>= 1)
        sc = fminf(sc, __shfl_xor_sync(0xffffffffu, sc, o));
    float thr = sc + 0.05f;

    // per-block lower bounds (lane b handles block b)
    float bmi = g_bmin[i * NBLK + lane];
    float bmj = g_bmin[j * NBLK + lane];
    float bound = fmaf(c2, bmj, c1 * bmi);
    unsigned mask = __ballot_sync(0xffffffffu, bound <= thr);

    float bestv = FLT_MAX;
    int   bidx  = 0x7fffffff;

    while (mask) {
        int b = __ffs(mask) - 1;
        mask &= mask - 1;
        int v = b * 32 + lane;
        float e = fmaf(c2, Afj[v], c1 * Afi[v]);
        // ascending b + strict < keeps the earliest index per lane
        if (e < bestv) { bestv = e; bidx = v; }
    }

    #pragma unroll
    for (int o = 16; o > 0; o >>= 1) {
        float ov = __shfl_xor_sync(0xffffffffu, bestv, o);
        int   oi = __shfl_xor_sync(0xffffffffu, bidx, o);
        if (ov < bestv || (ov == bestv && oi < bidx)) { bestv = ov; bidx = oi; }
    }
    if (lane == 0) {
        // Defensive: mathematically unreachable (winner's block always passes);
        // keeps a hypothetical logic bug finite/measurable instead of OOB->NaN.
        if (bidx == 0x7fffffff) bidx = min(i, j);
        g_idx[n] = bidx;
    }
}

// ---------------------------------------------------------------------------
// k_gather: out[b][d][t] = W[idx[b][t]][d]. CTA = 8 b's x 8 d's.
// W read directly (8 consecutive d's per code row = one 32B sector; W is
// L2-resident). Output writes are coalesced 1 KB runs.
// ---------------------------------------------------------------------------
__global__ __launch_bounds__(256) void k_gather(const float* __restrict__ W,
                                                float* __restrict__ out) {
    __shared__ float wt_s[8][V + 4];               // ~32 KB
    __shared__ __align__(16) int idx_s[8][TOK];    // 8 KB

    int t  = threadIdx.x;            // 0..255
    int b0 = blockIdx.x * 8;
    int d0 = blockIdx.y * 8;

    #pragma unroll
    for (int q = 0; q < 32; q++) {
        int lin = q * 256 + t;       // 0..8191
        int v  = lin >> 3;           // code row
        int dl = lin & 7;            // d offset
        wt_s[dl][v] = W[v * D + d0 + dl];
    }
    #pragma unroll
    for (int q = 0; q < 8; q++) {
        int lin = q * 256 + t;
        int bl = lin >> 8, tt = lin & 255;
        idx_s[bl][tt] = g_idx[(b0 + bl) * TOK + tt];
    }
    __syncthreads();

    #pragma unroll
    for (int bl = 0; bl < 8; bl++) {
        int myidx = min(max(idx_s[bl][t], 0), V - 1);   // defensive clamp
        #pragma unroll
        for (int dl = 0; dl < 8; dl++) {
            out[(((long)(b0 + bl) * D) + (d0 + dl)) * TOK + t] = wt_s[dl][myidx];
        }
    }
}

// ---------------------------------------------------------------------------
extern "C" void kernel_launch(void* const* d_in, const int* in_sizes, int n_in,
                              void* d_out, int out_size) {
    const int*   seq1  = (const int*)d_in[0];    // int32 words (int64 auto-detected)
    const int*   seq2  = (const int*)d_in[1];
    const float* alpha = (const float*)d_in[2];
    const float* W     = (const float*)d_in[3];
    float* out = (float*)d_out;

    k_decode<<<NQ / 256, 256>>>(seq1, seq2);      // 1: detect + decode + clamp
    k_gemmA_tri<<<NTRI, 256>>>(W);                // 2: symmetric A build (136 CTAs)
    k_blkmin<<<V / 8, 256>>>();                   // 3: per-block minima (warp/row)
    k_argmin_bb<<<NQ / 8, 256>>>(alpha);          // 4: branch-and-bound argmin
    dim3 grid(BB / 8, D / 8);
    k_gather<<<grid, 256>>>(W, out);              // 5: gather + BCHW layout
}

// round 17
// speedup vs baseline: 1.8005x; 1.1572x over previous
#include <cuda_runtime.h>
#include <cuda_bf16.h>
#include <float.h>

// Problem constants
#define BB   256      // batch
#define TOK  256      // tokens per image
#define NQ   (BB*TOK) // 65536 queries
#define V    1024     // codebook size
#define D    256      // code dim
#define NBLK 32       // 32 blocks of 32 codes per A row
#define NTIL 16       // 1024/64 tiles per dimension
#define NTRI 136      // NTIL*(NTIL+1)/2 upper-triangle tiles

// Device scratch (allocation-free rule: __device__ globals).
__device__ __align__(16) float g_A[V * V];        // A[r][v] = ||w_v||^2 - 2 w_r.w_v (4 MB)
__device__ __align__(16) float g_bmin[V * NBLK];  // per-row per-block exact fp32 min (128 KB)
__device__ __align__(16) int   g_idx[NQ];         // argmin per query

// monotone float -> uint map (order-preserving): min over keys = min over floats
__device__ __forceinline__ unsigned fmono(float f) {
    int u = __float_as_int(f);
    return (unsigned)(u ^ ((u >> 31) | 0x80000000));
}

// ---------------------------------------------------------------------------
// k_gemmA_bm: symmetric A build + fused per-block minima.
// dot(W[r],W[v]) is symmetric: only upper-triangle 64x64 tiles (bi <= bj).
//   direct:  A[r][v] = d_v - 2*dot   (r in bi-tile, v in bj-tile)
//   mirror:  A[v][r] = d_r - 2*dot
// Every (row, 32-col-block) of A is produced by exactly ONE tile (diagonal
// tiles double-write identical values), so each CTA also emits the exact
// fp32 block minima for the entries it owns — no atomics, no init pass.
// 256 threads, 4x4 register tile, BK=16. All fp32 exact.
// ---------------------------------------------------------------------------
__global__ __launch_bounds__(256) void k_gemmA_bm(const float* __restrict__ W) {
    __shared__ __align__(16) float As[16][64];   // [k][r]
    __shared__ __align__(16) float Bs[16][64];   // [k][v]
    __shared__ float nsa[64][4];                 // partial norms, r side
    __shared__ float nsb[64][4];                 // partial norms, v side
    __shared__ float pmm[64][17];                // mirror block-min partials (+1 pad)

    // triangle decode: blockIdx.x -> (bi, bj), bi <= bj
    int L = blockIdx.x;
    int bi = 0;
    while (L >= NTIL - bi) { L -= NTIL - bi; bi++; }
    int bj = bi + L;
    int r0 = bi * 64;
    int v0 = bj * 64;

    int tid = threadIdx.x;
    int tx = tid & 15;             // v direction
    int ty = tid >> 4;             // r direction

    float acc[4][4];
    #pragma unroll
    for (int i = 0; i < 4; i++)
        #pragma unroll
        for (int j = 0; j < 4; j++) acc[i][j] = 0.f;

    int lrow = tid >> 2;           // 0..63
    int lk4  = (tid & 3) * 4;      // 0,4,8,12
    float an = 0.f, bn = 0.f;

    for (int kt = 0; kt < D; kt += 16) {
        #pragma unroll
        for (int u = 0; u < 4; u++) {
            float av = W[(r0 + lrow) * D + kt + lk4 + u];
            float bv = W[(v0 + lrow) * D + kt + lk4 + u];
            As[lk4 + u][lrow] = av;
            Bs[lk4 + u][lrow] = bv;
            an = fmaf(av, av, an);
            bn = fmaf(bv, bv, bn);
        }
        __syncthreads();
        #pragma unroll
        for (int kk = 0; kk < 16; kk++) {
            float ar[4], br[4];
            #pragma unroll
            for (int i = 0; i < 4; i++) ar[i] = As[kk][ty * 4 + i];
            #pragma unroll
            for (int j = 0; j < 4; j++) br[j] = Bs[kk][tx * 4 + j];
            #pragma unroll
            for (int i = 0; i < 4; i++)
                #pragma unroll
                for (int j = 0; j < 4; j++)
                    acc[i][j] = fmaf(ar[i], br[j], acc[i][j]);
        }
        __syncthreads();
    }

    nsa[lrow][tid & 3] = an;
    nsb[lrow][tid & 3] = bn;
    __syncthreads();

    float dv[4], dr[4];
    #pragma unroll
    for (int u = 0; u < 4; u++) {
        int vv = tx * 4 + u;
        int rr = ty * 4 + u;
        dv[u] = nsb[vv][0] + nsb[vv][1] + nsb[vv][2] + nsb[vv][3];
        dr[u] = nsa[rr][0] + nsa[rr][1] + nsa[rr][2] + nsa[rr][3];
    }

    // ---- direct stores + direct block-min (min over v within 32-block) ----
    // thread's 4 v's (tx*4..tx*4+3) lie in one 32-block: blk = tx>>3.
    #pragma unroll
    for (int i = 0; i < 4; i++) {
        float4 o;
        o.x = dv[0] - 2.0f * acc[i][0];
        o.y = dv[1] - 2.0f * acc[i][1];
        o.z = dv[2] - 2.0f * acc[i][2];
        o.w = dv[3] - 2.0f * acc[i][3];
        int r = r0 + ty * 4 + i;
        *(float4*)(g_A + (size_t)r * V + v0 + tx * 4) = o;

        float m = fminf(fminf(o.x, o.y), fminf(o.z, o.w));
        // reduce over the 8 tx's of this block (lane bits 0..2 = tx bits 0..2)
        m = fminf(m, __shfl_xor_sync(0xffffffffu, m, 1));
        m = fminf(m, __shfl_xor_sync(0xffffffffu, m, 2));
        m = fminf(m, __shfl_xor_sync(0xffffffffu, m, 4));
        if ((tx & 7) == 0)
            g_bmin[r * NBLK + 2 * bj + (tx >> 3)] = m;
    }

    // ---- mirror stores + mirror block-min partials ----
    // mirror row v = v0+tx*4+j over columns r0+ty*4..+3 (block 2*bi + ty-range)
    #pragma unroll
    for (int j = 0; j < 4; j++) {
        float4 o;
        o.x = dr[0] - 2.0f * acc[0][j];
        o.y = dr[1] - 2.0f * acc[1][j];
        o.z = dr[2] - 2.0f * acc[2][j];
        o.w = dr[3] - 2.0f * acc[3][j];
        int v = v0 + tx * 4 + j;
        *(float4*)(g_A + (size_t)v * V + r0 + ty * 4) = o;
        pmm[tx * 4 + j][ty] = fminf(fminf(o.x, o.y), fminf(o.z, o.w));
    }
    __syncthreads();

    // reduce 16 ty-partials per mirror row; 64 rows handled by threads 0..63.
    // Mirror row v's columns r0..r0+63 span blocks 2*bi and 2*bi+1 ... but
    // each thread's partial covered 4 consecutive r's (one ty), so partials
    // with ty<8 belong to block 2*bi, ty>=8 to block 2*bi+1.
    if (tid < 64) {
        int vv = tid;
        float m0 = pmm[vv][0], m1 = pmm[vv][8];
        #pragma unroll
        for (int k = 1; k < 8; k++) {
            m0 = fminf(m0, pmm[vv][k]);
            m1 = fminf(m1, pmm[vv][k + 8]);
        }
        g_bmin[(v0 + vv) * NBLK + 2 * bi + 0] = m0;
        g_bmin[(v0 + vv) * NBLK + 2 * bi + 1] = m1;
    }
}

// ---------------------------------------------------------------------------
// k_argmin_bb: branch-and-bound argmin, one warp per query; dtype sniff and
// index decode fused in (ballot-based, no atomics).
//   score(v)  = c1*A[i][v] + c2*A[j][v]   (exact fp32 via fmaf)
//   m_hat     = min(score(i), score(j))   (every lane; broadcast loads)
//   bound_b   = c1*bmin_i[b] + c2*bmin_j[b] <= min score in block b
// Scan only blocks with bound_b <= m_hat + 0.05 (margin >> 3e-4 bound
// rounding; all real-score comparisons exact). Winner's block always passes.
// Final reduce: monotone-key REDUX min + lowest-index-among-ties REDUX.
// ---------------------------------------------------------------------------
__global__ __launch_bounds__(256) void k_argmin_bb(const int* __restrict__ s1,
                                                   const int* __restrict__ s2,
                                                   const float* __restrict__ alpha) {
    __shared__ unsigned sviol[8];
    int t = threadIdx.x;
    int warp = t >> 5;
    int lane = t & 31;

    // dtype sniff: int64 layout <=> odd words 0 and even words < V over the
    // first 256 int32 words (misclassify prob ~(1/1024)^128 for int32 data).
    int w = s1[t];
    bool viol = (t & 1) ? (w != 0) : ((unsigned)w >= V);
    unsigned vb = __ballot_sync(0xffffffffu, viol);
    if (lane == 0) sviol[warp] = vb;
    __syncthreads();
    unsigned anyv = sviol[0] | sviol[1] | sviol[2] | sviol[3]
                  | sviol[4] | sviol[5] | sviol[6] | sviol[7];
    int sh = anyv ? 0 : 1;           // 0: int32 layout, 1: int64 low word

    int n = blockIdx.x * 8 + warp;
    float a  = alpha[0];
    float c1 = 1.0f - a;
    float c2 = a;
    int i = min(max(s1[n << sh], 0), V - 1);   // broadcast loads
    int j = min(max(s2[n << sh], 0), V - 1);

    const float* Afi = g_A + (size_t)i * V;
    const float* Afj = g_A + (size_t)j * V;

    // upper bound: every lane, 4 broadcast loads, no shuffle chain
    float si = fmaf(c2, Afj[i], c1 * Afi[i]);
    float sj = fmaf(c2, Afj[j], c1 * Afi[j]);
    float thr = fminf(si, sj) + 0.05f;

    // per-block lower bounds (lane b handles block b)
    float bmi = g_bmin[i * NBLK + lane];
    float bmj = g_bmin[j * NBLK + lane];
    float bound = fmaf(c2, bmj, c1 * bmi);
    unsigned mask = __ballot_sync(0xffffffffu, bound <= thr);

    float bestv = FLT_MAX;
    int   bidx  = 0x7fffffff;

    while (mask) {
        int b = __ffs(mask) - 1;
        mask &= mask - 1;
        int v = b * 32 + lane;
        float e = fmaf(c2, Afj[v], c1 * Afi[v]);
        // ascending b + strict < keeps the earliest index per lane
        if (e < bestv) { bestv = e; bidx = v; }
    }

    // value min via monotone key, then lowest index among value-tied lanes
    unsigned key = fmono(bestv);
    unsigned mk  = __reduce_min_sync(0xffffffffu, key);
    unsigned cand = (key == mk) ? (unsigned)bidx : 0xffffffffu;
    unsigned win  = __reduce_min_sync(0xffffffffu, cand);

    if (lane == 0) {
        // Defensive: unreachable (winner's block always passes the bound);
        // keeps a hypothetical logic bug finite instead of OOB->NaN.
        if (win >= V) win = (unsigned)min(i, j);
        g_idx[n] = (int)win;
    }
}

// ---------------------------------------------------------------------------
// k_gather: out[b][d][t] = W[idx[b][t]][d]. CTA = 8 b's x 8 d's.
// W read directly (8 consecutive d's per code row = one 32B sector; W is
// L2-resident). Each thread emits 16 float4 stores (coalesced 1 KB runs).
// ---------------------------------------------------------------------------
__global__ __launch_bounds__(256) void k_gather(const float* __restrict__ W,
                                                float* __restrict__ out) {
    __shared__ float wt_s[8][V + 4];               // ~32 KB
    __shared__ __align__(16) int idx_s[8][TOK];    // 8 KB

    int t  = threadIdx.x;            // 0..255
    int b0 = blockIdx.x * 8;
    int d0 = blockIdx.y * 8;

    #pragma unroll
    for (int q = 0; q < 32; q++) {
        int lin = q * 256 + t;       // 0..8191
        int v  = lin >> 3;           // code row
        int dl = lin & 7;            // d offset
        wt_s[dl][v] = W[v * D + d0 + dl];
    }
    #pragma unroll
    for (int q = 0; q < 8; q++) {
        int lin = q * 256 + t;
        int bl = lin >> 8, tt = lin & 255;
        idx_s[bl][tt] = g_idx[(b0 + bl) * TOK + tt];
    }
    __syncthreads();

    int tt  = (t & 63) * 4;          // 4 consecutive tokens per thread
    int dlh = (t >> 6) * 2;          // 2 d-levels per thread

    #pragma unroll
    for (int bl = 0; bl < 8; bl++) {
        int4 iv = *(int4*)&idx_s[bl][tt];
        int i0 = min(max(iv.x, 0), V - 1);   // defensive clamps
        int i1 = min(max(iv.y, 0), V - 1);
        int i2 = min(max(iv.z, 0), V - 1);
        int i3 = min(max(iv.w, 0), V - 1);
        #pragma unroll
        for (int p = 0; p < 2; p++) {
            int dl = dlh + p;
            float4 o;
            o.x = wt_s[dl][i0];
            o.y = wt_s[dl][i1];
            o.z = wt_s[dl][i2];
            o.w = wt_s[dl][i3];
            *(float4*)(out + (((long)(b0 + bl) * D) + (d0 + dl)) * TOK + tt) = o;
        }
    }
}

// ---------------------------------------------------------------------------
extern "C" void kernel_launch(void* const* d_in, const int* in_sizes, int n_in,
                              void* d_out, int out_size) {
    const int*   seq1  = (const int*)d_in[0];    // int32 words (int64 auto-detected)
    const int*   seq2  = (const int*)d_in[1];
    const float* alpha = (const float*)d_in[2];
    const float* W     = (const float*)d_in[3];
    float* out = (float*)d_out;

    k_gemmA_bm<<<NTRI, 256>>>(W);                   // 1: A + block minima
    k_argmin_bb<<<NQ / 8, 256>>>(seq1, seq2, alpha);// 2: decode + B&B argmin
    dim3 grid(BB / 8, D / 8);
    k_gather<<<grid, 256>>>(W, out);                // 3: gather + BCHW layout
}